// round 9
// baseline (speedup 1.0000x reference)
#include <cuda_runtime.h>
#include <cuda_bf16.h>
#include <cstdint>

#define N_NODES 100000
#define E_MAX   1600000
#define FDIM 512
#define HDIM 64

// ---------------- scratch ----------------
__device__ __align__(128) float g_x1s[(size_t)N_NODES * HDIM];
__device__ __align__(128) float g_hs[(size_t)N_NODES * HDIM];
__device__ __align__(128) float g_agg2[(size_t)N_NODES * HDIM];
__device__ __align__(128) float g_norm_src[N_NODES];
__device__ __align__(128) float g_norm_dst[N_NODES];
__device__ __align__(128) unsigned short g_w1h[FDIM * HDIM];
__device__ __align__(128) unsigned short g_w1l[FDIM * HDIM];
__device__ __align__(128) unsigned short g_w2h[HDIM * FDIM];
__device__ __align__(128) unsigned short g_w2l[HDIM * FDIM];
__device__ int g_cnt_in[N_NODES];
__device__ int g_cnt_out[N_NODES];
__device__ int g_row_start[N_NODES + 1];
__device__ int g_cursor[N_NODES];
__device__ int g_esrc[E_MAX];
__device__ int g_bsum[256];
__device__ int g_is64;

// ---------------- helpers ----------------
__device__ __forceinline__ uint32_t smem_to_u32(const void* p) {
    uint32_t a;
    asm("{ .reg .u64 t; cvta.to.shared.u64 t, %1; cvt.u32.u64 %0, t; }" : "=r"(a) : "l"(p));
    return a;
}
__device__ __forceinline__ void ldsm4(uint32_t* r, uint32_t addr) {
    asm volatile("ldmatrix.sync.aligned.m8n8.x4.shared.b16 {%0,%1,%2,%3}, [%4];"
                 : "=r"(r[0]), "=r"(r[1]), "=r"(r[2]), "=r"(r[3]) : "r"(addr));
}
__device__ __forceinline__ void mma_bf16(float* c, const uint32_t* a, const uint32_t* b) {
    asm volatile(
        "mma.sync.aligned.m16n8k16.row.col.f32.bf16.bf16.f32 "
        "{%0,%1,%2,%3}, {%4,%5,%6,%7}, {%8,%9}, {%0,%1,%2,%3};"
        : "+f"(c[0]), "+f"(c[1]), "+f"(c[2]), "+f"(c[3])
        : "r"(a[0]), "r"(a[1]), "r"(a[2]), "r"(a[3]), "r"(b[0]), "r"(b[1]));
}
__device__ __forceinline__ void bf16split(float x, unsigned short& h, unsigned short& l) {
    __nv_bfloat16 bh = __float2bfloat16(x);
    float fh = __bfloat162float(bh);
    __nv_bfloat16 bl = __float2bfloat16(x - fh);
    h = __bfloat16_as_ushort(bh);
    l = __bfloat16_as_ushort(bl);
}

// ---------------- index width probe ----------------
__global__ void detect_kernel(const int* __restrict__ src32,
                              const int* __restrict__ dst32, int E) {
    if (threadIdx.x == 0 && blockIdx.x == 0) {
        int n = E < 256 ? E : 256;
        int is64 = 1;
        for (int i = 0; i < n; i++) {
            if (src32[2 * i + 1] != 0 || dst32[2 * i + 1] != 0) { is64 = 0; break; }
        }
        g_is64 = is64;
    }
}
__device__ __forceinline__ int load_idx(const void* p, int e, int is64) {
    if (is64) return (int)__ldg(reinterpret_cast<const long long*>(p) + e);
    return __ldg(reinterpret_cast<const int*>(p) + e);
}

// ---------------- weight pre-conversion (fp32 -> bf16 hi/lo) ----------------
__global__ __launch_bounds__(256) void wconv_kernel(const float* __restrict__ W1,
                                                    const float* __restrict__ W2) {
    int i = blockIdx.x * blockDim.x + threadIdx.x;
    if (i < FDIM * HDIM) {
        unsigned short h, l;
        bf16split(__ldg(&W1[i]), h, l);
        g_w1h[i] = h; g_w1l[i] = l;
        bf16split(__ldg(&W2[i]), h, l);
        g_w2h[i] = h; g_w2l[i] = l;
    }
}

// ---------------- graph build ----------------
__global__ __launch_bounds__(256) void zero_counts_kernel(int n) {
    int i = blockIdx.x * blockDim.x + threadIdx.x;
    if (i < n) { g_cnt_in[i] = 0; g_cnt_out[i] = 0; }
}
__global__ __launch_bounds__(256) void hist_kernel(const void* __restrict__ src,
                                                   const void* __restrict__ dst, int E) {
    int e = blockIdx.x * blockDim.x + threadIdx.x;
    if (e < E) {
        int is64 = g_is64;
        atomicAdd(&g_cnt_out[load_idx(src, e, is64)], 1);
        atomicAdd(&g_cnt_in[load_idx(dst, e, is64)], 1);
    }
}
__global__ __launch_bounds__(256) void scan1_kernel(int n) {
    __shared__ int sh[256];
    int tid = threadIdx.x;
    int base = blockIdx.x * 1024 + tid * 4;
    int v[4];
#pragma unroll
    for (int k = 0; k < 4; k++) v[k] = (base + k < n) ? g_cnt_in[base + k] : 0;
    int t = v[0] + v[1] + v[2] + v[3];
    sh[tid] = t;
    __syncthreads();
    for (int off = 1; off < 256; off <<= 1) {
        int x = (tid >= off) ? sh[tid - off] : 0;
        __syncthreads();
        sh[tid] += x;
        __syncthreads();
    }
    int run = sh[tid] - t;
#pragma unroll
    for (int k = 0; k < 4; k++) {
        if (base + k < n) g_row_start[base + k] = run;
        run += v[k];
    }
    if (tid == 255) g_bsum[blockIdx.x] = sh[255];
}
__global__ void scan2_kernel(int nb) {
    if (threadIdx.x == 0 && blockIdx.x == 0) {
        int running = 0;
        for (int b = 0; b < nb; b++) { int t = g_bsum[b]; g_bsum[b] = running; running += t; }
    }
}
// scan3 + norms fused
__global__ __launch_bounds__(256) void scan3_kernel(int n, int E) {
    int i = blockIdx.x * blockDim.x + threadIdx.x;
    if (i < n) {
        int v = g_row_start[i] + g_bsum[i >> 10];
        g_row_start[i] = v;
        g_cursor[i] = v;
        g_norm_src[i] = rsqrtf(fmaxf((float)g_cnt_out[i], 1.0f));
        g_norm_dst[i] = rsqrtf(fmaxf((float)g_cnt_in[i], 1.0f));
    }
    if (i == 0) g_row_start[n] = E;
}
__global__ __launch_bounds__(256) void fill_kernel(const void* __restrict__ src,
                                                   const void* __restrict__ dst, int E) {
    int e = blockIdx.x * blockDim.x + threadIdx.x;
    if (e < E) {
        int is64 = g_is64;
        int s = load_idx(src, e, is64);
        int d = load_idx(dst, e, is64);
        int pos = atomicAdd(&g_cursor[d], 1);
        g_esrc[pos] = s;
    }
}

// ---------------- aggregation (CSR, atomic-free) ----------------
template <int MODE>
__global__ __launch_bounds__(256) void agg_kernel(const float* __restrict__ msg,
                                                  float* __restrict__ outbuf, int n) {
    int node = blockIdx.x * 16 + (threadIdx.x >> 4);
    int c = threadIdx.x & 15;
    if (node >= n) return;
    int j = g_row_start[node];
    int s1 = g_row_start[node + 1];
    float4 acc = make_float4(0.f, 0.f, 0.f, 0.f);
    for (; j + 1 < s1; j += 2) {
        int sa = __ldg(&g_esrc[j]);
        int sb = __ldg(&g_esrc[j + 1]);
        float4 va = __ldg(reinterpret_cast<const float4*>(msg + (size_t)sa * HDIM + c * 4));
        float4 vb = __ldg(reinterpret_cast<const float4*>(msg + (size_t)sb * HDIM + c * 4));
        acc.x += va.x; acc.y += va.y; acc.z += va.z; acc.w += va.w;
        acc.x += vb.x; acc.y += vb.y; acc.z += vb.z; acc.w += vb.w;
    }
    if (j < s1) {
        int sa = __ldg(&g_esrc[j]);
        float4 va = __ldg(reinterpret_cast<const float4*>(msg + (size_t)sa * HDIM + c * 4));
        acc.x += va.x; acc.y += va.y; acc.z += va.z; acc.w += va.w;
    }
    float nd = g_norm_dst[node];
    float4 o;
    if (MODE == 0) {
        float ns = g_norm_src[node];
        o.x = fmaxf(acc.x * nd, 0.f) * ns;
        o.y = fmaxf(acc.y * nd, 0.f) * ns;
        o.z = fmaxf(acc.z * nd, 0.f) * ns;
        o.w = fmaxf(acc.w * nd, 0.f) * ns;
    } else {
        o.x = acc.x * nd; o.y = acc.y * nd; o.z = acc.z * nd; o.w = acc.w * nd;
    }
    reinterpret_cast<float4*>(outbuf)[(size_t)node * 16 + c] = o;
}

// ---------------- HMMA bf16-split GEMM (software-pipelined) ----------------
// C[M, N_total] = A[M, K] @ W[K, N_total] (W given pre-split as bf16 hi/lo).
// CTA tile 128x64, 8 warps 4(M)x2(N), warp tile 32x32, K chunks of 32.
// 3 passes: AhBh + AhBl + AlBh. Prefetch next chunk's A(fp32)/B(bf16) into regs
// while MMAs consume SMEM of current chunk.
#define AST 40
__global__ __launch_bounds__(256) void hmma_gemm_kernel(const float* __restrict__ A,
                                                        const unsigned short* __restrict__ Wh,
                                                        const unsigned short* __restrict__ Wl,
                                                        float* __restrict__ C,
                                                        int M, int K, int N_total,
                                                        const float* __restrict__ rsC) {
    __shared__ __align__(16) unsigned short sAh[128 * AST];
    __shared__ __align__(16) unsigned short sAl[128 * AST];
    __shared__ __align__(16) unsigned short sBh[64 * AST];
    __shared__ __align__(16) unsigned short sBl[64 * AST];

    const int tid = threadIdx.x;
    const int wid = tid >> 5, lid = tid & 31;
    const int wm = wid & 3, wn = wid >> 2;
    const int block_m = blockIdx.x * 128;
    const int n0 = blockIdx.y * 64;

    // prefetch registers
    float4 ra[4];
    uint4 rbh, rbl;
    const int a_r = tid >> 3;          // 0..31 (row block stride 32)
    const int a_c4 = tid & 7;          // float4 col
    const int b_kk = tid >> 3;         // 0..31
    const int b_n8 = (tid & 7) * 8;    // 0..56

    auto load_regs = [&](int k0) {
#pragma unroll
        for (int it = 0; it < 4; it++) {
            int gr = block_m + a_r + it * 32;
            ra[it] = (gr < M)
                ? __ldg(reinterpret_cast<const float4*>(A + (size_t)gr * K + k0 + a_c4 * 4))
                : make_float4(0.f, 0.f, 0.f, 0.f);
        }
        const unsigned short* ph = Wh + (size_t)(k0 + b_kk) * N_total + n0 + b_n8;
        const unsigned short* pl = Wl + (size_t)(k0 + b_kk) * N_total + n0 + b_n8;
        rbh = __ldg(reinterpret_cast<const uint4*>(ph));
        rbl = __ldg(reinterpret_cast<const uint4*>(pl));
    };
    auto store_smem = [&]() {
#pragma unroll
        for (int it = 0; it < 4; it++) {
            int r = a_r + it * 32;
            float fv[4] = {ra[it].x, ra[it].y, ra[it].z, ra[it].w};
            unsigned short h[4], l[4];
#pragma unroll
            for (int q = 0; q < 4; q++) bf16split(fv[q], h[q], l[q]);
            uint2 uh = make_uint2((uint32_t)h[0] | ((uint32_t)h[1] << 16),
                                  (uint32_t)h[2] | ((uint32_t)h[3] << 16));
            uint2 ul = make_uint2((uint32_t)l[0] | ((uint32_t)l[1] << 16),
                                  (uint32_t)l[2] | ((uint32_t)l[3] << 16));
            *reinterpret_cast<uint2*>(&sAh[r * AST + a_c4 * 4]) = uh;
            *reinterpret_cast<uint2*>(&sAl[r * AST + a_c4 * 4]) = ul;
        }
        const unsigned short* ph = reinterpret_cast<const unsigned short*>(&rbh);
        const unsigned short* pl = reinterpret_cast<const unsigned short*>(&rbl);
#pragma unroll
        for (int i = 0; i < 8; i++) {
            sBh[(b_n8 + i) * AST + b_kk] = ph[i];
            sBl[(b_n8 + i) * AST + b_kk] = pl[i];
        }
    };

    float acc[2][4][4];
#pragma unroll
    for (int i = 0; i < 2; i++)
#pragma unroll
        for (int j = 0; j < 4; j++)
#pragma unroll
            for (int q = 0; q < 4; q++) acc[i][j][q] = 0.f;

    const uint32_t aH = smem_to_u32(sAh);
    const uint32_t aL = smem_to_u32(sAl);
    const uint32_t bH = smem_to_u32(sBh);
    const uint32_t bL = smem_to_u32(sBl);

    load_regs(0);
    for (int k0 = 0; k0 < K; k0 += 32) {
        store_smem();
        __syncthreads();
        if (k0 + 32 < K) load_regs(k0 + 32);  // prefetch next chunk during MMAs

#pragma unroll
        for (int ks = 0; ks < 32; ks += 16) {
            uint32_t ah[2][4], al[2][4], bh[4][2], bl[4][2];
#pragma unroll
            for (int mf = 0; mf < 2; mf++) {
                uint32_t rowA = wm * 32 + mf * 16 + (lid & 15);
                uint32_t off = (rowA * AST + ks + (lid >> 4) * 8) * 2;
                ldsm4(ah[mf], aH + off);
                ldsm4(al[mf], aL + off);
            }
#pragma unroll
            for (int p = 0; p < 2; p++) {
                uint32_t nrow = wn * 32 + p * 16 + ((lid >> 4) & 1) * 8 + (lid & 7);
                uint32_t off = (nrow * AST + ks + ((lid >> 3) & 1) * 8) * 2;
                uint32_t r[4];
                ldsm4(r, bH + off);
                bh[2 * p][0] = r[0]; bh[2 * p][1] = r[1];
                bh[2 * p + 1][0] = r[2]; bh[2 * p + 1][1] = r[3];
                ldsm4(r, bL + off);
                bl[2 * p][0] = r[0]; bl[2 * p][1] = r[1];
                bl[2 * p + 1][0] = r[2]; bl[2 * p + 1][1] = r[3];
            }
#pragma unroll
            for (int mf = 0; mf < 2; mf++)
#pragma unroll
                for (int nf = 0; nf < 4; nf++) {
                    mma_bf16(acc[mf][nf], ah[mf], bh[nf]);
                    mma_bf16(acc[mf][nf], ah[mf], bl[nf]);
                    mma_bf16(acc[mf][nf], al[mf], bh[nf]);
                }
        }
        __syncthreads();
    }

    // ---- epilogue ----
    int lrow = lid >> 2;
    int lcol = (lid & 3) * 2;
#pragma unroll
    for (int mf = 0; mf < 2; mf++) {
#pragma unroll
        for (int half = 0; half < 2; half++) {
            int row = block_m + wm * 32 + mf * 16 + lrow + half * 8;
            if (row < M) {
                float s = rsC ? __ldg(&rsC[row]) : 1.0f;
#pragma unroll
                for (int nf = 0; nf < 4; nf++) {
                    int col = n0 + wn * 32 + nf * 8 + lcol;
                    float2 o = make_float2(acc[mf][nf][half * 2] * s,
                                           acc[mf][nf][half * 2 + 1] * s);
                    *reinterpret_cast<float2*>(C + (size_t)row * N_total + col) = o;
                }
            }
        }
    }
}

// ---------------- launch ----------------
extern "C" void kernel_launch(void* const* d_in, const int* in_sizes, int n_in,
                              void* d_out, int out_size) {
    const float* features = (const float*)d_in[0];
    const void* src = d_in[1];
    const void* dst = d_in[2];
    const float* W1 = (const float*)d_in[3];
    const float* W2 = (const float*)d_in[4];
    float* out = (float*)d_out;

    const int N = N_NODES;
    const int E = in_sizes[1];

    float *p_x1s, *p_hs, *p_agg2, *p_ns;
    unsigned short *p_w1h, *p_w1l, *p_w2h, *p_w2l;
    cudaGetSymbolAddress((void**)&p_x1s, g_x1s);
    cudaGetSymbolAddress((void**)&p_hs, g_hs);
    cudaGetSymbolAddress((void**)&p_agg2, g_agg2);
    cudaGetSymbolAddress((void**)&p_ns, g_norm_src);
    cudaGetSymbolAddress((void**)&p_w1h, g_w1h);
    cudaGetSymbolAddress((void**)&p_w1l, g_w1l);
    cudaGetSymbolAddress((void**)&p_w2h, g_w2h);
    cudaGetSymbolAddress((void**)&p_w2l, g_w2l);

    const int nb_scan = (N + 1023) / 1024;

    detect_kernel<<<1, 32>>>((const int*)src, (const int*)dst, E);
    wconv_kernel<<<(FDIM * HDIM + 255) / 256, 256>>>(W1, W2);
    zero_counts_kernel<<<(N + 255) / 256, 256>>>(N);
    hist_kernel<<<(E + 255) / 256, 256>>>(src, dst, E);
    scan1_kernel<<<nb_scan, 256>>>(N);
    scan2_kernel<<<1, 32>>>(nb_scan);
    scan3_kernel<<<(N + 255) / 256, 256>>>(N, E);
    fill_kernel<<<(E + 255) / 256, 256>>>(src, dst, E);

    const int mtiles = (N + 127) / 128;
    {
        dim3 grid(mtiles, 1);
        hmma_gemm_kernel<<<grid, 256>>>(features, p_w1h, p_w1l, p_x1s, N, FDIM, HDIM, p_ns);
    }
    agg_kernel<0><<<(N + 15) / 16, 256>>>(p_x1s, p_hs, N);
    agg_kernel<1><<<(N + 15) / 16, 256>>>(p_hs, p_agg2, N);
    {
        dim3 grid(mtiles, FDIM / 64);
        hmma_gemm_kernel<<<grid, 256>>>(p_agg2, p_w2h, p_w2l, out, N, HDIM, FDIM, nullptr);
    }
}

// round 10
// speedup vs baseline: 1.2339x; 1.2339x over previous
#include <cuda_runtime.h>
#include <cuda_bf16.h>
#include <cstdint>

#define N_NODES 100000
#define E_MAX   1600000
#define FDIM 512
#define HDIM 64

// ---------------- scratch ----------------
__device__ __align__(128) float g_x1s[(size_t)N_NODES * HDIM];
__device__ __align__(128) float g_hs[(size_t)N_NODES * HDIM];
__device__ __align__(128) unsigned short g_a2h[(size_t)N_NODES * HDIM];  // agg2*nd hi
__device__ __align__(128) unsigned short g_a2l[(size_t)N_NODES * HDIM];  // agg2*nd lo
__device__ __align__(128) float g_norm_src[N_NODES];
__device__ __align__(128) float g_norm_dst[N_NODES];
// W1^T [64][512] hi/lo, W2^T [512][64] hi/lo
__device__ __align__(128) unsigned short g_w1ht[HDIM * FDIM];
__device__ __align__(128) unsigned short g_w1lt[HDIM * FDIM];
__device__ __align__(128) unsigned short g_w2ht[FDIM * HDIM];
__device__ __align__(128) unsigned short g_w2lt[FDIM * HDIM];
__device__ int g_cnt_in[N_NODES];
__device__ int g_cnt_out[N_NODES];
__device__ int g_row_start[N_NODES + 1];
__device__ int g_cursor[N_NODES];
__device__ int g_esrc[E_MAX];
__device__ int g_bsum[256];
__device__ int g_is64;

// ---------------- helpers ----------------
__device__ __forceinline__ uint32_t smem_to_u32(const void* p) {
    uint32_t a;
    asm("{ .reg .u64 t; cvta.to.shared.u64 t, %1; cvt.u32.u64 %0, t; }" : "=r"(a) : "l"(p));
    return a;
}
__device__ __forceinline__ void ldsm4(uint32_t* r, uint32_t addr) {
    asm volatile("ldmatrix.sync.aligned.m8n8.x4.shared.b16 {%0,%1,%2,%3}, [%4];"
                 : "=r"(r[0]), "=r"(r[1]), "=r"(r[2]), "=r"(r[3]) : "r"(addr));
}
__device__ __forceinline__ void mma_bf16(float* c, const uint32_t* a, const uint32_t* b) {
    asm volatile(
        "mma.sync.aligned.m16n8k16.row.col.f32.bf16.bf16.f32 "
        "{%0,%1,%2,%3}, {%4,%5,%6,%7}, {%8,%9}, {%0,%1,%2,%3};"
        : "+f"(c[0]), "+f"(c[1]), "+f"(c[2]), "+f"(c[3])
        : "r"(a[0]), "r"(a[1]), "r"(a[2]), "r"(a[3]), "r"(b[0]), "r"(b[1]));
}
// paired fp32 -> bf16 hi/lo split (x low half, y high half)
__device__ __forceinline__ void split2(float x, float y, uint32_t& h2, uint32_t& l2) {
    __nv_bfloat162 bh = __floats2bfloat162_rn(x, y);
    float2 f = __bfloat1622float2(bh);
    __nv_bfloat162 bl = __floats2bfloat162_rn(x - f.x, y - f.y);
    h2 = reinterpret_cast<uint32_t&>(bh);
    l2 = reinterpret_cast<uint32_t&>(bl);
}
__device__ __forceinline__ void bf16split(float x, unsigned short& h, unsigned short& l) {
    __nv_bfloat16 bh = __float2bfloat16(x);
    float fh = __bfloat162float(bh);
    __nv_bfloat16 bl = __float2bfloat16(x - fh);
    h = __bfloat16_as_ushort(bh);
    l = __bfloat16_as_ushort(bl);
}

// ---------------- index width probe ----------------
__global__ void detect_kernel(const int* __restrict__ src32,
                              const int* __restrict__ dst32, int E) {
    if (threadIdx.x == 0 && blockIdx.x == 0) {
        int n = E < 256 ? E : 256;
        int is64 = 1;
        for (int i = 0; i < n; i++) {
            if (src32[2 * i + 1] != 0 || dst32[2 * i + 1] != 0) { is64 = 0; break; }
        }
        g_is64 = is64;
    }
}
__device__ __forceinline__ int load_idx(const void* p, int e, int is64) {
    if (is64) return (int)__ldg(reinterpret_cast<const long long*>(p) + e);
    return __ldg(reinterpret_cast<const int*>(p) + e);
}

// ---------------- weight pre-conversion: transpose + bf16 hi/lo split ----------------
__global__ __launch_bounds__(256) void wconv_kernel(const float* __restrict__ W1,
                                                    const float* __restrict__ W2) {
    int i = blockIdx.x * blockDim.x + threadIdx.x;
    if (i < FDIM * HDIM) {
        unsigned short h, l;
        // W1 [k][n] (k<512, n<64) -> W1t [n][k]
        {
            int k = i >> 6, n = i & 63;
            bf16split(__ldg(&W1[i]), h, l);
            g_w1ht[n * FDIM + k] = h;
            g_w1lt[n * FDIM + k] = l;
        }
        // W2 [k][n] (k<64, n<512) -> W2t [n][k]
        {
            int k = i >> 9, n = i & 511;
            bf16split(__ldg(&W2[i]), h, l);
            g_w2ht[n * HDIM + k] = h;
            g_w2lt[n * HDIM + k] = l;
        }
    }
}

// ---------------- graph build ----------------
__global__ __launch_bounds__(256) void zero_counts_kernel(int n) {
    int i = blockIdx.x * blockDim.x + threadIdx.x;
    if (i < n) { g_cnt_in[i] = 0; g_cnt_out[i] = 0; }
}
__global__ __launch_bounds__(256) void hist_kernel(const void* __restrict__ src,
                                                   const void* __restrict__ dst, int E) {
    int e = blockIdx.x * blockDim.x + threadIdx.x;
    if (e < E) {
        int is64 = g_is64;
        atomicAdd(&g_cnt_out[load_idx(src, e, is64)], 1);
        atomicAdd(&g_cnt_in[load_idx(dst, e, is64)], 1);
    }
}
__global__ __launch_bounds__(256) void scan1_kernel(int n) {
    __shared__ int sh[256];
    int tid = threadIdx.x;
    int base = blockIdx.x * 1024 + tid * 4;
    int v[4];
#pragma unroll
    for (int k = 0; k < 4; k++) v[k] = (base + k < n) ? g_cnt_in[base + k] : 0;
    int t = v[0] + v[1] + v[2] + v[3];
    sh[tid] = t;
    __syncthreads();
    for (int off = 1; off < 256; off <<= 1) {
        int x = (tid >= off) ? sh[tid - off] : 0;
        __syncthreads();
        sh[tid] += x;
        __syncthreads();
    }
    int run = sh[tid] - t;
#pragma unroll
    for (int k = 0; k < 4; k++) {
        if (base + k < n) g_row_start[base + k] = run;
        run += v[k];
    }
    if (tid == 255) g_bsum[blockIdx.x] = sh[255];
}
__global__ void scan2_kernel(int nb) {
    if (threadIdx.x == 0 && blockIdx.x == 0) {
        int running = 0;
        for (int b = 0; b < nb; b++) { int t = g_bsum[b]; g_bsum[b] = running; running += t; }
    }
}
__global__ __launch_bounds__(256) void scan3_kernel(int n, int E) {
    int i = blockIdx.x * blockDim.x + threadIdx.x;
    if (i < n) {
        int v = g_row_start[i] + g_bsum[i >> 10];
        g_row_start[i] = v;
        g_cursor[i] = v;
        g_norm_src[i] = rsqrtf(fmaxf((float)g_cnt_out[i], 1.0f));
        g_norm_dst[i] = rsqrtf(fmaxf((float)g_cnt_in[i], 1.0f));
    }
    if (i == 0) g_row_start[n] = E;
}
__global__ __launch_bounds__(256) void fill_kernel(const void* __restrict__ src,
                                                   const void* __restrict__ dst, int E) {
    int e = blockIdx.x * blockDim.x + threadIdx.x;
    if (e < E) {
        int is64 = g_is64;
        int s = load_idx(src, e, is64);
        int d = load_idx(dst, e, is64);
        int pos = atomicAdd(&g_cursor[d], 1);
        g_esrc[pos] = s;
    }
}

// ---------------- aggregation (CSR, atomic-free) ----------------
// MODE 0: hs = relu(sum*nd)*ns (fp32 out)
// MODE 1: agg2 = sum*nd, written directly as bf16 hi/lo split (for GEMM2)
template <int MODE>
__global__ __launch_bounds__(256) void agg_kernel(const float* __restrict__ msg,
                                                  float* __restrict__ outf,
                                                  unsigned short* __restrict__ outh,
                                                  unsigned short* __restrict__ outl,
                                                  int n) {
    int node = blockIdx.x * 16 + (threadIdx.x >> 4);
    int c = threadIdx.x & 15;
    if (node >= n) return;
    int j = g_row_start[node];
    int s1 = g_row_start[node + 1];
    float4 acc = make_float4(0.f, 0.f, 0.f, 0.f);
    for (; j + 1 < s1; j += 2) {
        int sa = __ldg(&g_esrc[j]);
        int sb = __ldg(&g_esrc[j + 1]);
        float4 va = __ldg(reinterpret_cast<const float4*>(msg + (size_t)sa * HDIM + c * 4));
        float4 vb = __ldg(reinterpret_cast<const float4*>(msg + (size_t)sb * HDIM + c * 4));
        acc.x += va.x; acc.y += va.y; acc.z += va.z; acc.w += va.w;
        acc.x += vb.x; acc.y += vb.y; acc.z += vb.z; acc.w += vb.w;
    }
    if (j < s1) {
        int sa = __ldg(&g_esrc[j]);
        float4 va = __ldg(reinterpret_cast<const float4*>(msg + (size_t)sa * HDIM + c * 4));
        acc.x += va.x; acc.y += va.y; acc.z += va.z; acc.w += va.w;
    }
    float nd = g_norm_dst[node];
    if (MODE == 0) {
        float ns = g_norm_src[node];
        float4 o;
        o.x = fmaxf(acc.x * nd, 0.f) * ns;
        o.y = fmaxf(acc.y * nd, 0.f) * ns;
        o.z = fmaxf(acc.z * nd, 0.f) * ns;
        o.w = fmaxf(acc.w * nd, 0.f) * ns;
        reinterpret_cast<float4*>(outf)[(size_t)node * 16 + c] = o;
    } else {
        uint32_t h01, l01, h23, l23;
        split2(acc.x * nd, acc.y * nd, h01, l01);
        split2(acc.z * nd, acc.w * nd, h23, l23);
        size_t off = ((size_t)node * HDIM + c * 4) >> 1;  // uint32 index
        reinterpret_cast<uint2*>(outh)[off >> 1] = make_uint2(h01, h23);
        reinterpret_cast<uint2*>(outl)[off >> 1] = make_uint2(l01, l23);
    }
}

// ---------------- GEMM1: C[M,64] = A(fp32)[M,512] @ W1, rsC row scale ----------------
// CTA 128x64, 8 warps 4(M)x2(N), K chunks of 32, 3-pass bf16 split.
#define AST 40
__global__ __launch_bounds__(256) void gemm1_kernel(const float* __restrict__ A,
                                                    const unsigned short* __restrict__ Bth,
                                                    const unsigned short* __restrict__ Btl,
                                                    float* __restrict__ C,
                                                    int M, const float* __restrict__ rsC) {
    __shared__ __align__(16) unsigned short sAh[128 * AST];
    __shared__ __align__(16) unsigned short sAl[128 * AST];
    __shared__ __align__(16) unsigned short sBh[64 * AST];
    __shared__ __align__(16) unsigned short sBl[64 * AST];

    const int tid = threadIdx.x;
    const int wid = tid >> 5, lid = tid & 31;
    const int wm = wid & 3, wn = wid >> 2;
    const int block_m = blockIdx.x * 128;

    float acc[2][4][4];
#pragma unroll
    for (int i = 0; i < 2; i++)
#pragma unroll
        for (int j = 0; j < 4; j++)
#pragma unroll
            for (int q = 0; q < 4; q++) acc[i][j][q] = 0.f;

    const uint32_t aH = smem_to_u32(sAh);
    const uint32_t aL = smem_to_u32(sAl);
    const uint32_t bH = smem_to_u32(sBh);
    const uint32_t bL = smem_to_u32(sBl);

    // B copy mapping: row n = tid>>2 (0..63), k8 = (tid&3)*8
    const int b_n = tid >> 2, b_k8 = (tid & 3) * 8;
    // A load mapping: float4 f -> r = f>>3, c4 = f&7
    for (int k0 = 0; k0 < FDIM; k0 += 32) {
        // ---- A: 128x32 fp32 -> split hi/lo ----
#pragma unroll
        for (int it = 0; it < 4; it++) {
            int f = it * 256 + tid;
            int r = f >> 3, c4 = f & 7;
            int gr = block_m + r;
            float4 v = make_float4(0.f, 0.f, 0.f, 0.f);
            if (gr < M)
                v = __ldg(reinterpret_cast<const float4*>(A + (size_t)gr * FDIM + k0 + c4 * 4));
            uint32_t h01, l01, h23, l23;
            split2(v.x, v.y, h01, l01);
            split2(v.z, v.w, h23, l23);
            *reinterpret_cast<uint2*>(&sAh[r * AST + c4 * 4]) = make_uint2(h01, h23);
            *reinterpret_cast<uint2*>(&sAl[r * AST + c4 * 4]) = make_uint2(l01, l23);
        }
        // ---- B: pure uint4 copy from pre-split transposed weights ----
        {
            const size_t go = (size_t)b_n * FDIM + k0 + b_k8;
            uint4 vh = __ldg(reinterpret_cast<const uint4*>(Bth + go));
            uint4 vl = __ldg(reinterpret_cast<const uint4*>(Btl + go));
            *reinterpret_cast<uint4*>(&sBh[b_n * AST + b_k8]) = vh;
            *reinterpret_cast<uint4*>(&sBl[b_n * AST + b_k8]) = vl;
        }
        __syncthreads();

#pragma unroll
        for (int ks = 0; ks < 32; ks += 16) {
            uint32_t ah[2][4], al[2][4], bh[4][2], bl[4][2];
#pragma unroll
            for (int mf = 0; mf < 2; mf++) {
                uint32_t rowA = wm * 32 + mf * 16 + (lid & 15);
                uint32_t off = (rowA * AST + ks + (lid >> 4) * 8) * 2;
                ldsm4(ah[mf], aH + off);
                ldsm4(al[mf], aL + off);
            }
#pragma unroll
            for (int p = 0; p < 2; p++) {
                uint32_t nrow = wn * 32 + p * 16 + ((lid >> 4) & 1) * 8 + (lid & 7);
                uint32_t off = (nrow * AST + ks + ((lid >> 3) & 1) * 8) * 2;
                uint32_t r[4];
                ldsm4(r, bH + off);
                bh[2 * p][0] = r[0]; bh[2 * p][1] = r[1];
                bh[2 * p + 1][0] = r[2]; bh[2 * p + 1][1] = r[3];
                ldsm4(r, bL + off);
                bl[2 * p][0] = r[0]; bl[2 * p][1] = r[1];
                bl[2 * p + 1][0] = r[2]; bl[2 * p + 1][1] = r[3];
            }
#pragma unroll
            for (int mf = 0; mf < 2; mf++)
#pragma unroll
                for (int nf = 0; nf < 4; nf++) {
                    mma_bf16(acc[mf][nf], ah[mf], bh[nf]);
                    mma_bf16(acc[mf][nf], ah[mf], bl[nf]);
                    mma_bf16(acc[mf][nf], al[mf], bh[nf]);
                }
        }
        __syncthreads();
    }

    int lrow = lid >> 2, lcol = (lid & 3) * 2;
#pragma unroll
    for (int mf = 0; mf < 2; mf++)
#pragma unroll
        for (int half = 0; half < 2; half++) {
            int row = block_m + wm * 32 + mf * 16 + lrow + half * 8;
            if (row < M) {
                float s = __ldg(&rsC[row]);
#pragma unroll
                for (int nf = 0; nf < 4; nf++) {
                    int col = wn * 32 + nf * 8 + lcol;
                    float2 o = make_float2(acc[mf][nf][half * 2] * s,
                                           acc[mf][nf][half * 2 + 1] * s);
                    *reinterpret_cast<float2*>(C + (size_t)row * HDIM + col) = o;
                }
            }
        }
}

// ---------------- GEMM2: C[M,512] = A(pre-split bf16)[M,64] @ W2 ----------------
// Same tile shape; A tiles are pure copies (zero conversion). K = 64 (2 chunks).
__global__ __launch_bounds__(256) void gemm2_kernel(const unsigned short* __restrict__ Ah,
                                                    const unsigned short* __restrict__ Al,
                                                    const unsigned short* __restrict__ Bth,
                                                    const unsigned short* __restrict__ Btl,
                                                    float* __restrict__ C, int M) {
    __shared__ __align__(16) unsigned short sAh[128 * AST];
    __shared__ __align__(16) unsigned short sAl[128 * AST];
    __shared__ __align__(16) unsigned short sBh[64 * AST];
    __shared__ __align__(16) unsigned short sBl[64 * AST];

    const int tid = threadIdx.x;
    const int wid = tid >> 5, lid = tid & 31;
    const int wm = wid & 3, wn = wid >> 2;
    const int block_m = blockIdx.x * 128;
    const int n0 = blockIdx.y * 64;

    float acc[2][4][4];
#pragma unroll
    for (int i = 0; i < 2; i++)
#pragma unroll
        for (int j = 0; j < 4; j++)
#pragma unroll
            for (int q = 0; q < 4; q++) acc[i][j][q] = 0.f;

    const uint32_t aH = smem_to_u32(sAh);
    const uint32_t aL = smem_to_u32(sAl);
    const uint32_t bH = smem_to_u32(sBh);
    const uint32_t bL = smem_to_u32(sBl);

    const int b_n = tid >> 2, b_k8 = (tid & 3) * 8;
    for (int k0 = 0; k0 < HDIM; k0 += 32) {
        // ---- A: pure uint4 copy (128 rows x 32 shorts = 512 uint4 per array) ----
#pragma unroll
        for (int it = 0; it < 2; it++) {
            int u = it * 256 + tid;
            int r = u >> 2, q8 = (u & 3) * 8;
            int gr = block_m + r;
            uint4 vh = make_uint4(0, 0, 0, 0), vl = make_uint4(0, 0, 0, 0);
            if (gr < M) {
                size_t go = (size_t)gr * HDIM + k0 + q8;
                vh = __ldg(reinterpret_cast<const uint4*>(Ah + go));
                vl = __ldg(reinterpret_cast<const uint4*>(Al + go));
            }
            *reinterpret_cast<uint4*>(&sAh[r * AST + q8]) = vh;
            *reinterpret_cast<uint4*>(&sAl[r * AST + q8]) = vl;
        }
        // ---- B copy ----
        {
            const size_t go = (size_t)(n0 + b_n) * HDIM + k0 + b_k8;
            uint4 vh = __ldg(reinterpret_cast<const uint4*>(Bth + go));
            uint4 vl = __ldg(reinterpret_cast<const uint4*>(Btl + go));
            *reinterpret_cast<uint4*>(&sBh[b_n * AST + b_k8]) = vh;
            *reinterpret_cast<uint4*>(&sBl[b_n * AST + b_k8]) = vl;
        }
        __syncthreads();

#pragma unroll
        for (int ks = 0; ks < 32; ks += 16) {
            uint32_t ah[2][4], al[2][4], bh[4][2], bl[4][2];
#pragma unroll
            for (int mf = 0; mf < 2; mf++) {
                uint32_t rowA = wm * 32 + mf * 16 + (lid & 15);
                uint32_t off = (rowA * AST + ks + (lid >> 4) * 8) * 2;
                ldsm4(ah[mf], aH + off);
                ldsm4(al[mf], aL + off);
            }
#pragma unroll
            for (int p = 0; p < 2; p++) {
                uint32_t nrow = wn * 32 + p * 16 + ((lid >> 4) & 1) * 8 + (lid & 7);
                uint32_t off = (nrow * AST + ks + ((lid >> 3) & 1) * 8) * 2;
                uint32_t r[4];
                ldsm4(r, bH + off);
                bh[2 * p][0] = r[0]; bh[2 * p][1] = r[1];
                bh[2 * p + 1][0] = r[2]; bh[2 * p + 1][1] = r[3];
                ldsm4(r, bL + off);
                bl[2 * p][0] = r[0]; bl[2 * p][1] = r[1];
                bl[2 * p + 1][0] = r[2]; bl[2 * p + 1][1] = r[3];
            }
#pragma unroll
            for (int mf = 0; mf < 2; mf++)
#pragma unroll
                for (int nf = 0; nf < 4; nf++) {
                    mma_bf16(acc[mf][nf], ah[mf], bh[nf]);
                    mma_bf16(acc[mf][nf], ah[mf], bl[nf]);
                    mma_bf16(acc[mf][nf], al[mf], bh[nf]);
                }
        }
        __syncthreads();
    }

    int lrow = lid >> 2, lcol = (lid & 3) * 2;
#pragma unroll
    for (int mf = 0; mf < 2; mf++)
#pragma unroll
        for (int half = 0; half < 2; half++) {
            int row = block_m + wm * 32 + mf * 16 + lrow + half * 8;
            if (row < M) {
#pragma unroll
                for (int nf = 0; nf < 4; nf++) {
                    int col = n0 + wn * 32 + nf * 8 + lcol;
                    float2 o = make_float2(acc[mf][nf][half * 2],
                                           acc[mf][nf][half * 2 + 1]);
                    *reinterpret_cast<float2*>(C + (size_t)row * FDIM + col) = o;
                }
            }
        }
}

// ---------------- launch ----------------
extern "C" void kernel_launch(void* const* d_in, const int* in_sizes, int n_in,
                              void* d_out, int out_size) {
    const float* features = (const float*)d_in[0];
    const void* src = d_in[1];
    const void* dst = d_in[2];
    const float* W1 = (const float*)d_in[3];
    const float* W2 = (const float*)d_in[4];
    float* out = (float*)d_out;

    const int N = N_NODES;
    const int E = in_sizes[1];

    float *p_x1s, *p_hs, *p_ns;
    unsigned short *p_a2h, *p_a2l, *p_w1ht, *p_w1lt, *p_w2ht, *p_w2lt;
    cudaGetSymbolAddress((void**)&p_x1s, g_x1s);
    cudaGetSymbolAddress((void**)&p_hs, g_hs);
    cudaGetSymbolAddress((void**)&p_ns, g_norm_src);
    cudaGetSymbolAddress((void**)&p_a2h, g_a2h);
    cudaGetSymbolAddress((void**)&p_a2l, g_a2l);
    cudaGetSymbolAddress((void**)&p_w1ht, g_w1ht);
    cudaGetSymbolAddress((void**)&p_w1lt, g_w1lt);
    cudaGetSymbolAddress((void**)&p_w2ht, g_w2ht);
    cudaGetSymbolAddress((void**)&p_w2lt, g_w2lt);

    const int nb_scan = (N + 1023) / 1024;

    detect_kernel<<<1, 32>>>((const int*)src, (const int*)dst, E);
    wconv_kernel<<<(FDIM * HDIM + 255) / 256, 256>>>(W1, W2);
    zero_counts_kernel<<<(N + 255) / 256, 256>>>(N);
    hist_kernel<<<(E + 255) / 256, 256>>>(src, dst, E);
    scan1_kernel<<<nb_scan, 256>>>(N);
    scan2_kernel<<<1, 32>>>(nb_scan);
    scan3_kernel<<<(N + 255) / 256, 256>>>(N, E);
    fill_kernel<<<(E + 255) / 256, 256>>>(src, dst, E);

    const int mtiles = (N + 127) / 128;
    // layer 1: x1s = (X @ W1) * ns
    gemm1_kernel<<<mtiles, 256>>>(features, p_w1ht, p_w1lt, p_x1s, N, p_ns);
    // hs = relu(agg1 * nd) * ns
    agg_kernel<0><<<(N + 15) / 16, 256>>>(p_x1s, p_hs, nullptr, nullptr, N);
    // agg2 = (sum hs) * nd, written pre-split bf16 hi/lo
    agg_kernel<1><<<(N + 15) / 16, 256>>>(p_hs, nullptr, p_a2h, p_a2l, N);
    // out = agg2 @ W2
    {
        dim3 grid(mtiles, FDIM / 64);
        gemm2_kernel<<<grid, 256>>>(p_a2h, p_a2l, p_w2ht, p_w2lt, out, N);
    }
}

// round 11
// speedup vs baseline: 1.3135x; 1.0645x over previous
#include <cuda_runtime.h>
#include <cuda_bf16.h>
#include <cstdint>

#define N_NODES 100000
#define E_MAX   1600000
#define FDIM 512
#define HDIM 64

// ---------------- scratch ----------------
__device__ __align__(128) float g_x1s[(size_t)N_NODES * HDIM];
__device__ __align__(128) float g_hs[(size_t)N_NODES * HDIM];
__device__ __align__(128) unsigned short g_a2h[(size_t)N_NODES * HDIM];  // agg2*nd hi
__device__ __align__(128) unsigned short g_a2l[(size_t)N_NODES * HDIM];  // agg2*nd lo
__device__ __align__(128) float g_norm_src[N_NODES];
__device__ __align__(128) float g_norm_dst[N_NODES];
// W1^T [64][512] hi/lo, W2^T [512][64] hi/lo
__device__ __align__(128) unsigned short g_w1ht[HDIM * FDIM];
__device__ __align__(128) unsigned short g_w1lt[HDIM * FDIM];
__device__ __align__(128) unsigned short g_w2ht[FDIM * HDIM];
__device__ __align__(128) unsigned short g_w2lt[FDIM * HDIM];
__device__ int g_cnt_in[N_NODES];
__device__ int g_cnt_out[N_NODES];
__device__ int g_row_start[N_NODES + 1];
__device__ int g_cursor[N_NODES];
__device__ int g_esrc[E_MAX];
__device__ int g_bsum[256];
__device__ int g_is64;

// ---------------- helpers ----------------
__device__ __forceinline__ uint32_t smem_to_u32(const void* p) {
    uint32_t a;
    asm("{ .reg .u64 t; cvta.to.shared.u64 t, %1; cvt.u32.u64 %0, t; }" : "=r"(a) : "l"(p));
    return a;
}
__device__ __forceinline__ void ldsm4(uint32_t* r, uint32_t addr) {
    asm volatile("ldmatrix.sync.aligned.m8n8.x4.shared.b16 {%0,%1,%2,%3}, [%4];"
                 : "=r"(r[0]), "=r"(r[1]), "=r"(r[2]), "=r"(r[3]) : "r"(addr));
}
__device__ __forceinline__ void mma_bf16(float* c, const uint32_t* a, const uint32_t* b) {
    asm volatile(
        "mma.sync.aligned.m16n8k16.row.col.f32.bf16.bf16.f32 "
        "{%0,%1,%2,%3}, {%4,%5,%6,%7}, {%8,%9}, {%0,%1,%2,%3};"
        : "+f"(c[0]), "+f"(c[1]), "+f"(c[2]), "+f"(c[3])
        : "r"(a[0]), "r"(a[1]), "r"(a[2]), "r"(a[3]), "r"(b[0]), "r"(b[1]));
}
__device__ __forceinline__ void split2(float x, float y, uint32_t& h2, uint32_t& l2) {
    __nv_bfloat162 bh = __floats2bfloat162_rn(x, y);
    float2 f = __bfloat1622float2(bh);
    __nv_bfloat162 bl = __floats2bfloat162_rn(x - f.x, y - f.y);
    h2 = reinterpret_cast<uint32_t&>(bh);
    l2 = reinterpret_cast<uint32_t&>(bl);
}
__device__ __forceinline__ void bf16split(float x, unsigned short& h, unsigned short& l) {
    __nv_bfloat16 bh = __float2bfloat16(x);
    float fh = __bfloat162float(bh);
    __nv_bfloat16 bl = __float2bfloat16(x - fh);
    h = __bfloat16_as_ushort(bh);
    l = __bfloat16_as_ushort(bl);
}
__device__ __forceinline__ int load_idx(const void* p, int e, int is64) {
    if (is64) return (int)__ldg(reinterpret_cast<const long long*>(p) + e);
    return __ldg(reinterpret_cast<const int*>(p) + e);
}

// ---------------- zero counters + index width probe (fused) ----------------
__global__ __launch_bounds__(256) void zero_counts_kernel(const int* __restrict__ src32,
                                                          const int* __restrict__ dst32,
                                                          int n, int E) {
    int i = blockIdx.x * blockDim.x + threadIdx.x;
    if (i < n) { g_cnt_in[i] = 0; g_cnt_out[i] = 0; }
    if (i == 0) {
        int m = E < 256 ? E : 256;
        int is64 = 1;
        for (int k = 0; k < m; k++) {
            if (src32[2 * k + 1] != 0 || dst32[2 * k + 1] != 0) { is64 = 0; break; }
        }
        g_is64 = is64;
    }
}

// ---------------- weight pre-conversion: transpose + bf16 hi/lo split ----------------
__global__ __launch_bounds__(256) void wconv_kernel(const float* __restrict__ W1,
                                                    const float* __restrict__ W2) {
    int i = blockIdx.x * blockDim.x + threadIdx.x;
    if (i < FDIM * HDIM) {
        unsigned short h, l;
        {
            int k = i >> 6, n = i & 63;
            bf16split(__ldg(&W1[i]), h, l);
            g_w1ht[n * FDIM + k] = h;
            g_w1lt[n * FDIM + k] = l;
        }
        {
            int k = i >> 9, n = i & 511;
            bf16split(__ldg(&W2[i]), h, l);
            g_w2ht[n * HDIM + k] = h;
            g_w2lt[n * HDIM + k] = l;
        }
    }
}

// ---------------- graph build ----------------
__global__ __launch_bounds__(256) void hist_kernel(const void* __restrict__ src,
                                                   const void* __restrict__ dst, int E) {
    int e = blockIdx.x * blockDim.x + threadIdx.x;
    if (e < E) {
        int is64 = g_is64;
        atomicAdd(&g_cnt_out[load_idx(src, e, is64)], 1);
        atomicAdd(&g_cnt_in[load_idx(dst, e, is64)], 1);
    }
}
__global__ __launch_bounds__(256) void scan1_kernel(int n) {
    __shared__ int sh[256];
    int tid = threadIdx.x;
    int base = blockIdx.x * 1024 + tid * 4;
    int v[4];
#pragma unroll
    for (int k = 0; k < 4; k++) v[k] = (base + k < n) ? g_cnt_in[base + k] : 0;
    int t = v[0] + v[1] + v[2] + v[3];
    sh[tid] = t;
    __syncthreads();
    for (int off = 1; off < 256; off <<= 1) {
        int x = (tid >= off) ? sh[tid - off] : 0;
        __syncthreads();
        sh[tid] += x;
        __syncthreads();
    }
    int run = sh[tid] - t;
#pragma unroll
    for (int k = 0; k < 4; k++) {
        if (base + k < n) g_row_start[base + k] = run;
        run += v[k];
    }
    if (tid == 255) g_bsum[blockIdx.x] = sh[255];
}
__global__ void scan2_kernel(int nb) {
    if (threadIdx.x == 0 && blockIdx.x == 0) {
        int running = 0;
        for (int b = 0; b < nb; b++) { int t = g_bsum[b]; g_bsum[b] = running; running += t; }
    }
}
__global__ __launch_bounds__(256) void scan3_kernel(int n, int E) {
    int i = blockIdx.x * blockDim.x + threadIdx.x;
    if (i < n) {
        int v = g_row_start[i] + g_bsum[i >> 10];
        g_row_start[i] = v;
        g_cursor[i] = v;
        g_norm_src[i] = rsqrtf(fmaxf((float)g_cnt_out[i], 1.0f));
        g_norm_dst[i] = rsqrtf(fmaxf((float)g_cnt_in[i], 1.0f));
    }
    if (i == 0) g_row_start[n] = E;
}
__global__ __launch_bounds__(256) void fill_kernel(const void* __restrict__ src,
                                                   const void* __restrict__ dst, int E) {
    int e = blockIdx.x * blockDim.x + threadIdx.x;
    if (e < E) {
        int is64 = g_is64;
        int s = load_idx(src, e, is64);
        int d = load_idx(dst, e, is64);
        int pos = atomicAdd(&g_cursor[d], 1);
        g_esrc[pos] = s;
    }
}

// ---------------- aggregation (CSR, atomic-free) ----------------
template <int MODE>
__global__ __launch_bounds__(256) void agg_kernel(const float* __restrict__ msg,
                                                  float* __restrict__ outf,
                                                  unsigned short* __restrict__ outh,
                                                  unsigned short* __restrict__ outl,
                                                  int n) {
    int node = blockIdx.x * 16 + (threadIdx.x >> 4);
    int c = threadIdx.x & 15;
    if (node >= n) return;
    int j = g_row_start[node];
    int s1 = g_row_start[node + 1];
    float4 acc = make_float4(0.f, 0.f, 0.f, 0.f);
    for (; j + 1 < s1; j += 2) {
        int sa = __ldg(&g_esrc[j]);
        int sb = __ldg(&g_esrc[j + 1]);
        float4 va = __ldg(reinterpret_cast<const float4*>(msg + (size_t)sa * HDIM + c * 4));
        float4 vb = __ldg(reinterpret_cast<const float4*>(msg + (size_t)sb * HDIM + c * 4));
        acc.x += va.x; acc.y += va.y; acc.z += va.z; acc.w += va.w;
        acc.x += vb.x; acc.y += vb.y; acc.z += vb.z; acc.w += vb.w;
    }
    if (j < s1) {
        int sa = __ldg(&g_esrc[j]);
        float4 va = __ldg(reinterpret_cast<const float4*>(msg + (size_t)sa * HDIM + c * 4));
        acc.x += va.x; acc.y += va.y; acc.z += va.z; acc.w += va.w;
    }
    float nd = g_norm_dst[node];
    if (MODE == 0) {
        float ns = g_norm_src[node];
        float4 o;
        o.x = fmaxf(acc.x * nd, 0.f) * ns;
        o.y = fmaxf(acc.y * nd, 0.f) * ns;
        o.z = fmaxf(acc.z * nd, 0.f) * ns;
        o.w = fmaxf(acc.w * nd, 0.f) * ns;
        reinterpret_cast<float4*>(outf)[(size_t)node * 16 + c] = o;
    } else {
        uint32_t h01, l01, h23, l23;
        split2(acc.x * nd, acc.y * nd, h01, l01);
        split2(acc.z * nd, acc.w * nd, h23, l23);
        size_t off = ((size_t)node * HDIM + c * 4) >> 2;  // uint2 index
        reinterpret_cast<uint2*>(outh)[off] = make_uint2(h01, h23);
        reinterpret_cast<uint2*>(outl)[off] = make_uint2(l01, l23);
    }
}

// ---------------- GEMM1: C[M,64] = A(fp32)[M,512] @ W1, rsC row scale ----------------
#define AST 40
__global__ __launch_bounds__(256) void gemm1_kernel(const float* __restrict__ A,
                                                    const unsigned short* __restrict__ Bth,
                                                    const unsigned short* __restrict__ Btl,
                                                    float* __restrict__ C,
                                                    int M, const float* __restrict__ rsC) {
    __shared__ __align__(16) unsigned short sAh[128 * AST];
    __shared__ __align__(16) unsigned short sAl[128 * AST];
    __shared__ __align__(16) unsigned short sBh[64 * AST];
    __shared__ __align__(16) unsigned short sBl[64 * AST];

    const int tid = threadIdx.x;
    const int wid = tid >> 5, lid = tid & 31;
    const int wm = wid & 3, wn = wid >> 2;
    const int block_m = blockIdx.x * 128;

    float acc[2][4][4];
#pragma unroll
    for (int i = 0; i < 2; i++)
#pragma unroll
        for (int j = 0; j < 4; j++)
#pragma unroll
            for (int q = 0; q < 4; q++) acc[i][j][q] = 0.f;

    const uint32_t aH = smem_to_u32(sAh);
    const uint32_t aL = smem_to_u32(sAl);
    const uint32_t bH = smem_to_u32(sBh);
    const uint32_t bL = smem_to_u32(sBl);

    const int b_n = tid >> 2, b_k8 = (tid & 3) * 8;
    for (int k0 = 0; k0 < FDIM; k0 += 32) {
#pragma unroll
        for (int it = 0; it < 4; it++) {
            int f = it * 256 + tid;
            int r = f >> 3, c4 = f & 7;
            int gr = block_m + r;
            float4 v = make_float4(0.f, 0.f, 0.f, 0.f);
            if (gr < M)
                v = __ldg(reinterpret_cast<const float4*>(A + (size_t)gr * FDIM + k0 + c4 * 4));
            uint32_t h01, l01, h23, l23;
            split2(v.x, v.y, h01, l01);
            split2(v.z, v.w, h23, l23);
            *reinterpret_cast<uint2*>(&sAh[r * AST + c4 * 4]) = make_uint2(h01, h23);
            *reinterpret_cast<uint2*>(&sAl[r * AST + c4 * 4]) = make_uint2(l01, l23);
        }
        {
            const size_t go = (size_t)b_n * FDIM + k0 + b_k8;
            uint4 vh = __ldg(reinterpret_cast<const uint4*>(Bth + go));
            uint4 vl = __ldg(reinterpret_cast<const uint4*>(Btl + go));
            *reinterpret_cast<uint4*>(&sBh[b_n * AST + b_k8]) = vh;
            *reinterpret_cast<uint4*>(&sBl[b_n * AST + b_k8]) = vl;
        }
        __syncthreads();

#pragma unroll
        for (int ks = 0; ks < 32; ks += 16) {
            uint32_t ah[2][4], al[2][4], bh[4][2], bl[4][2];
#pragma unroll
            for (int mf = 0; mf < 2; mf++) {
                uint32_t rowA = wm * 32 + mf * 16 + (lid & 15);
                uint32_t off = (rowA * AST + ks + (lid >> 4) * 8) * 2;
                ldsm4(ah[mf], aH + off);
                ldsm4(al[mf], aL + off);
            }
#pragma unroll
            for (int p = 0; p < 2; p++) {
                uint32_t nrow = wn * 32 + p * 16 + ((lid >> 4) & 1) * 8 + (lid & 7);
                uint32_t off = (nrow * AST + ks + ((lid >> 3) & 1) * 8) * 2;
                uint32_t r[4];
                ldsm4(r, bH + off);
                bh[2 * p][0] = r[0]; bh[2 * p][1] = r[1];
                bh[2 * p + 1][0] = r[2]; bh[2 * p + 1][1] = r[3];
                ldsm4(r, bL + off);
                bl[2 * p][0] = r[0]; bl[2 * p][1] = r[1];
                bl[2 * p + 1][0] = r[2]; bl[2 * p + 1][1] = r[3];
            }
#pragma unroll
            for (int mf = 0; mf < 2; mf++)
#pragma unroll
                for (int nf = 0; nf < 4; nf++) {
                    mma_bf16(acc[mf][nf], ah[mf], bh[nf]);
                    mma_bf16(acc[mf][nf], ah[mf], bl[nf]);
                    mma_bf16(acc[mf][nf], al[mf], bh[nf]);
                }
        }
        __syncthreads();
    }

    int lrow = lid >> 2, lcol = (lid & 3) * 2;
#pragma unroll
    for (int mf = 0; mf < 2; mf++)
#pragma unroll
        for (int half = 0; half < 2; half++) {
            int row = block_m + wm * 32 + mf * 16 + lrow + half * 8;
            if (row < M) {
                float s = __ldg(&rsC[row]);
#pragma unroll
                for (int nf = 0; nf < 4; nf++) {
                    int col = wn * 32 + nf * 8 + lcol;
                    float2 o = make_float2(acc[mf][nf][half * 2] * s,
                                           acc[mf][nf][half * 2 + 1] * s);
                    *reinterpret_cast<float2*>(C + (size_t)row * HDIM + col) = o;
                }
            }
        }
}

// ---------------- GEMM2: C[M,512] = A(pre-split bf16)[M,64] @ W2 ----------------
// One CTA per 128-row m-tile. A (128x64 hi/lo) loaded into SMEM ONCE; loop over
// all 8 N-tiles of 64 internally (B tiles streamed from L2). Dynamic SMEM.
#define AST2 72
#define G2_SMEM (2 * 128 * AST2 * 2 + 2 * 64 * AST2 * 2)
__global__ __launch_bounds__(256) void gemm2_kernel(const unsigned short* __restrict__ Ah,
                                                    const unsigned short* __restrict__ Al,
                                                    const unsigned short* __restrict__ Bth,
                                                    const unsigned short* __restrict__ Btl,
                                                    float* __restrict__ C, int M) {
    extern __shared__ __align__(16) unsigned short dyn[];
    unsigned short* sAh = dyn;                    // 128*AST2
    unsigned short* sAl = sAh + 128 * AST2;
    unsigned short* sBh = sAl + 128 * AST2;       // 64*AST2
    unsigned short* sBl = sBh + 64 * AST2;

    const int tid = threadIdx.x;
    const int wid = tid >> 5, lid = tid & 31;
    const int wm = wid & 3, wn = wid >> 2;
    const int block_m = blockIdx.x * 128;

    const uint32_t aH = smem_to_u32(sAh);
    const uint32_t aL = smem_to_u32(sAl);
    const uint32_t bH = smem_to_u32(sBh);
    const uint32_t bL = smem_to_u32(sBl);

    // ---- load A once: 128 rows x 64 shorts = 1024 uint4 per array ----
#pragma unroll
    for (int it = 0; it < 4; it++) {
        int u = it * 256 + tid;
        int r = u >> 3, q8 = (u & 7) * 8;
        int gr = block_m + r;
        uint4 vh = make_uint4(0, 0, 0, 0), vl = make_uint4(0, 0, 0, 0);
        if (gr < M) {
            size_t go = (size_t)gr * HDIM + q8;
            vh = __ldg(reinterpret_cast<const uint4*>(Ah + go));
            vl = __ldg(reinterpret_cast<const uint4*>(Al + go));
        }
        *reinterpret_cast<uint4*>(&sAh[r * AST2 + q8]) = vh;
        *reinterpret_cast<uint4*>(&sAl[r * AST2 + q8]) = vl;
    }

    const int b_n = tid >> 1, b_k8 = (tid & 1) * 8;  // n: 0..127? no: 64 rows, 8 uint4 each
    // B tile: 64 rows x 64 shorts = 512 uint4 per array; 256 threads -> 2 iters
    int lrow = lid >> 2, lcol = (lid & 3) * 2;

    for (int nt = 0; nt < FDIM / 64; nt++) {
        const int n0 = nt * 64;
        __syncthreads();  // A ready (first iter) / previous MMAs done (later iters)
        // ---- load B tile ----
#pragma unroll
        for (int it = 0; it < 2; it++) {
            int u = it * 256 + tid;
            int r = u >> 3, q8 = (u & 7) * 8;
            size_t go = (size_t)(n0 + r) * HDIM + q8;
            uint4 vh = __ldg(reinterpret_cast<const uint4*>(Bth + go));
            uint4 vl = __ldg(reinterpret_cast<const uint4*>(Btl + go));
            *reinterpret_cast<uint4*>(&sBh[r * AST2 + q8]) = vh;
            *reinterpret_cast<uint4*>(&sBl[r * AST2 + q8]) = vl;
        }
        __syncthreads();

        float acc[2][4][4];
#pragma unroll
        for (int i = 0; i < 2; i++)
#pragma unroll
            for (int j = 0; j < 4; j++)
#pragma unroll
                for (int q = 0; q < 4; q++) acc[i][j][q] = 0.f;

#pragma unroll
        for (int ks = 0; ks < 64; ks += 16) {
            uint32_t ah[2][4], al[2][4], bh[4][2], bl[4][2];
#pragma unroll
            for (int mf = 0; mf < 2; mf++) {
                uint32_t rowA = wm * 32 + mf * 16 + (lid & 15);
                uint32_t off = (rowA * AST2 + ks + (lid >> 4) * 8) * 2;
                ldsm4(ah[mf], aH + off);
                ldsm4(al[mf], aL + off);
            }
#pragma unroll
            for (int p = 0; p < 2; p++) {
                uint32_t nrow = wn * 32 + p * 16 + ((lid >> 4) & 1) * 8 + (lid & 7);
                uint32_t off = (nrow * AST2 + ks + ((lid >> 3) & 1) * 8) * 2;
                uint32_t r[4];
                ldsm4(r, bH + off);
                bh[2 * p][0] = r[0]; bh[2 * p][1] = r[1];
                bh[2 * p + 1][0] = r[2]; bh[2 * p + 1][1] = r[3];
                ldsm4(r, bL + off);
                bl[2 * p][0] = r[0]; bl[2 * p][1] = r[1];
                bl[2 * p + 1][0] = r[2]; bl[2 * p + 1][1] = r[3];
            }
#pragma unroll
            for (int mf = 0; mf < 2; mf++)
#pragma unroll
                for (int nf = 0; nf < 4; nf++) {
                    mma_bf16(acc[mf][nf], ah[mf], bh[nf]);
                    mma_bf16(acc[mf][nf], ah[mf], bl[nf]);
                    mma_bf16(acc[mf][nf], al[mf], bh[nf]);
                }
        }

        // ---- epilogue for this N tile ----
#pragma unroll
        for (int mf = 0; mf < 2; mf++)
#pragma unroll
            for (int half = 0; half < 2; half++) {
                int row = block_m + wm * 32 + mf * 16 + lrow + half * 8;
                if (row < M) {
#pragma unroll
                    for (int nf = 0; nf < 4; nf++) {
                        int col = n0 + wn * 32 + nf * 8 + lcol;
                        float2 o = make_float2(acc[mf][nf][half * 2],
                                               acc[mf][nf][half * 2 + 1]);
                        *reinterpret_cast<float2*>(C + (size_t)row * FDIM + col) = o;
                    }
                }
            }
    }
}

// ---------------- launch ----------------
extern "C" void kernel_launch(void* const* d_in, const int* in_sizes, int n_in,
                              void* d_out, int out_size) {
    const float* features = (const float*)d_in[0];
    const void* src = d_in[1];
    const void* dst = d_in[2];
    const float* W1 = (const float*)d_in[3];
    const float* W2 = (const float*)d_in[4];
    float* out = (float*)d_out;

    const int N = N_NODES;
    const int E = in_sizes[1];

    float *p_x1s, *p_hs, *p_ns;
    unsigned short *p_a2h, *p_a2l, *p_w1ht, *p_w1lt, *p_w2ht, *p_w2lt;
    cudaGetSymbolAddress((void**)&p_x1s, g_x1s);
    cudaGetSymbolAddress((void**)&p_hs, g_hs);
    cudaGetSymbolAddress((void**)&p_ns, g_norm_src);
    cudaGetSymbolAddress((void**)&p_a2h, g_a2h);
    cudaGetSymbolAddress((void**)&p_a2l, g_a2l);
    cudaGetSymbolAddress((void**)&p_w1ht, g_w1ht);
    cudaGetSymbolAddress((void**)&p_w1lt, g_w1lt);
    cudaGetSymbolAddress((void**)&p_w2ht, g_w2ht);
    cudaGetSymbolAddress((void**)&p_w2lt, g_w2lt);

    cudaFuncSetAttribute(gemm2_kernel, cudaFuncAttributeMaxDynamicSharedMemorySize, G2_SMEM);

    const int nb_scan = (N + 1023) / 1024;

    zero_counts_kernel<<<(N + 255) / 256, 256>>>((const int*)src, (const int*)dst, N, E);
    wconv_kernel<<<(FDIM * HDIM + 255) / 256, 256>>>(W1, W2);
    hist_kernel<<<(E + 255) / 256, 256>>>(src, dst, E);
    scan1_kernel<<<nb_scan, 256>>>(N);
    scan2_kernel<<<1, 32>>>(nb_scan);
    scan3_kernel<<<(N + 255) / 256, 256>>>(N, E);
    fill_kernel<<<(E + 255) / 256, 256>>>(src, dst, E);

    const int mtiles = (N + 127) / 128;
    gemm1_kernel<<<mtiles, 256>>>(features, p_w1ht, p_w1lt, p_x1s, N, p_ns);
    agg_kernel<0><<<(N + 15) / 16, 256>>>(p_x1s, p_hs, nullptr, nullptr, N);
    agg_kernel<1><<<(N + 15) / 16, 256>>>(p_hs, nullptr, p_a2h, p_a2l, N);
    gemm2_kernel<<<mtiles, 256, G2_SMEM>>>(p_a2h, p_a2l, p_w2ht, p_w2lt, out, N);
}

// round 12
// speedup vs baseline: 1.4701x; 1.1192x over previous
#include <cuda_runtime.h>
#include <cuda_bf16.h>
#include <cstdint>

#define N_NODES 100000
#define E_MAX   1600000
#define FDIM 512
#define HDIM 64

// ---------------- scratch ----------------
__device__ __align__(128) float g_x1g[(size_t)N_NODES * HDIM];   // X@W1 (UNscaled)
__device__ __align__(128) float g_hs[(size_t)N_NODES * HDIM];    // relu(agg1*nd)*ns
__device__ __align__(128) unsigned short g_a2h[(size_t)N_NODES * HDIM];
__device__ __align__(128) unsigned short g_a2l[(size_t)N_NODES * HDIM];
__device__ __align__(128) float g_norm_src[N_NODES];
__device__ __align__(128) float g_norm_dst[N_NODES];
__device__ __align__(128) unsigned short g_w1ht[HDIM * FDIM];
__device__ __align__(128) unsigned short g_w1lt[HDIM * FDIM];
__device__ __align__(128) unsigned short g_w2ht[FDIM * HDIM];
__device__ __align__(128) unsigned short g_w2lt[FDIM * HDIM];
__device__ int g_cnt_in[N_NODES];
__device__ int g_cnt_out[N_NODES];
__device__ int g_row_start[N_NODES + 1];
__device__ int g_cursor[N_NODES];
__device__ int g_esrc[E_MAX];
__device__ int g_bsum[256];
__device__ int g_is64;

// ---------------- helpers ----------------
__device__ __forceinline__ uint32_t smem_to_u32(const void* p) {
    uint32_t a;
    asm("{ .reg .u64 t; cvta.to.shared.u64 t, %1; cvt.u32.u64 %0, t; }" : "=r"(a) : "l"(p));
    return a;
}
__device__ __forceinline__ void ldsm4(uint32_t* r, uint32_t addr) {
    asm volatile("ldmatrix.sync.aligned.m8n8.x4.shared.b16 {%0,%1,%2,%3}, [%4];"
                 : "=r"(r[0]), "=r"(r[1]), "=r"(r[2]), "=r"(r[3]) : "r"(addr));
}
__device__ __forceinline__ void mma_bf16(float* c, const uint32_t* a, const uint32_t* b) {
    asm volatile(
        "mma.sync.aligned.m16n8k16.row.col.f32.bf16.bf16.f32 "
        "{%0,%1,%2,%3}, {%4,%5,%6,%7}, {%8,%9}, {%0,%1,%2,%3};"
        : "+f"(c[0]), "+f"(c[1]), "+f"(c[2]), "+f"(c[3])
        : "r"(a[0]), "r"(a[1]), "r"(a[2]), "r"(a[3]), "r"(b[0]), "r"(b[1]));
}
__device__ __forceinline__ void split2(float x, float y, uint32_t& h2, uint32_t& l2) {
    __nv_bfloat162 bh = __floats2bfloat162_rn(x, y);
    float2 f = __bfloat1622float2(bh);
    __nv_bfloat162 bl = __floats2bfloat162_rn(x - f.x, y - f.y);
    h2 = reinterpret_cast<uint32_t&>(bh);
    l2 = reinterpret_cast<uint32_t&>(bl);
}
__device__ __forceinline__ void bf16split(float x, unsigned short& h, unsigned short& l) {
    __nv_bfloat16 bh = __float2bfloat16(x);
    float fh = __bfloat162float(bh);
    __nv_bfloat16 bl = __float2bfloat16(x - fh);
    h = __bfloat16_as_ushort(bh);
    l = __bfloat16_as_ushort(bl);
}
__device__ __forceinline__ int load_idx(const void* p, int e, int is64) {
    if (is64) return (int)__ldg(reinterpret_cast<const long long*>(p) + e);
    return __ldg(reinterpret_cast<const int*>(p) + e);
}

// ---------------- zero counters + index width probe (fused) ----------------
__global__ __launch_bounds__(256) void zero_counts_kernel(const int* __restrict__ src32,
                                                          const int* __restrict__ dst32,
                                                          int n, int E) {
    int i = blockIdx.x * blockDim.x + threadIdx.x;
    if (i < n) { g_cnt_in[i] = 0; g_cnt_out[i] = 0; }
    if (i == 0) {
        int m = E < 256 ? E : 256;
        int is64 = 1;
        for (int k = 0; k < m; k++) {
            if (src32[2 * k + 1] != 0 || dst32[2 * k + 1] != 0) { is64 = 0; break; }
        }
        g_is64 = is64;
    }
}

// ---------------- weight pre-conversion: transpose + bf16 hi/lo split ----------------
__global__ __launch_bounds__(256) void wconv_kernel(const float* __restrict__ W1,
                                                    const float* __restrict__ W2) {
    int i = blockIdx.x * blockDim.x + threadIdx.x;
    if (i < FDIM * HDIM) {
        unsigned short h, l;
        {
            int k = i >> 6, n = i & 63;
            bf16split(__ldg(&W1[i]), h, l);
            g_w1ht[n * FDIM + k] = h;
            g_w1lt[n * FDIM + k] = l;
        }
        {
            int k = i >> 9, n = i & 511;
            bf16split(__ldg(&W2[i]), h, l);
            g_w2ht[n * HDIM + k] = h;
            g_w2lt[n * HDIM + k] = l;
        }
    }
}

// ---------------- graph build ----------------
__global__ __launch_bounds__(256) void hist_kernel(const void* __restrict__ src,
                                                   const void* __restrict__ dst, int E) {
    int e = blockIdx.x * blockDim.x + threadIdx.x;
    if (e < E) {
        int is64 = g_is64;
        atomicAdd(&g_cnt_out[load_idx(src, e, is64)], 1);
        atomicAdd(&g_cnt_in[load_idx(dst, e, is64)], 1);
    }
}
__global__ __launch_bounds__(256) void scan1_kernel(int n) {
    __shared__ int sh[256];
    int tid = threadIdx.x;
    int base = blockIdx.x * 1024 + tid * 4;
    int v[4];
#pragma unroll
    for (int k = 0; k < 4; k++) v[k] = (base + k < n) ? g_cnt_in[base + k] : 0;
    int t = v[0] + v[1] + v[2] + v[3];
    sh[tid] = t;
    __syncthreads();
    for (int off = 1; off < 256; off <<= 1) {
        int x = (tid >= off) ? sh[tid - off] : 0;
        __syncthreads();
        sh[tid] += x;
        __syncthreads();
    }
    int run = sh[tid] - t;
#pragma unroll
    for (int k = 0; k < 4; k++) {
        if (base + k < n) g_row_start[base + k] = run;
        run += v[k];
    }
    if (tid == 255) g_bsum[blockIdx.x] = sh[255];
}
// parallel exclusive scan over <=256 block sums
__global__ void scan2_kernel(int nb) {
    __shared__ int sh[256];
    int t = threadIdx.x;
    int v = (t < nb) ? g_bsum[t] : 0;
    sh[t] = v;
    __syncthreads();
    for (int off = 1; off < 256; off <<= 1) {
        int x = (t >= off) ? sh[t - off] : 0;
        __syncthreads();
        sh[t] += x;
        __syncthreads();
    }
    if (t < nb) g_bsum[t] = sh[t] - v;
}
__global__ __launch_bounds__(256) void scan3_kernel(int n, int E) {
    int i = blockIdx.x * blockDim.x + threadIdx.x;
    if (i < n) {
        int v = g_row_start[i] + g_bsum[i >> 10];
        g_row_start[i] = v;
        g_cursor[i] = v;
        g_norm_src[i] = rsqrtf(fmaxf((float)g_cnt_out[i], 1.0f));
        g_norm_dst[i] = rsqrtf(fmaxf((float)g_cnt_in[i], 1.0f));
    }
    if (i == 0) g_row_start[n] = E;
}
__global__ __launch_bounds__(256) void fill_kernel(const void* __restrict__ src,
                                                   const void* __restrict__ dst, int E) {
    int e = blockIdx.x * blockDim.x + threadIdx.x;
    if (e < E) {
        int is64 = g_is64;
        int s = load_idx(src, e, is64);
        int d = load_idx(dst, e, is64);
        int pos = atomicAdd(&g_cursor[d], 1);
        g_esrc[pos] = s;
    }
}

// ---------------- aggregation (CSR, atomic-free) ----------------
// MODE 0: msg is UNscaled X@W1; apply ns[src] during gather:
//         out = relu((sum ns[sa]*msg[sa]) * nd) * ns
// MODE 1: msg fully scaled; out = (sum msg[sa]) * nd, bf16 hi/lo split
template <int MODE>
__global__ __launch_bounds__(256) void agg_kernel(const float* __restrict__ msg,
                                                  float* __restrict__ outf,
                                                  unsigned short* __restrict__ outh,
                                                  unsigned short* __restrict__ outl,
                                                  int n) {
    int node = blockIdx.x * 16 + (threadIdx.x >> 4);
    int c = threadIdx.x & 15;
    if (node >= n) return;
    int j = g_row_start[node];
    int s1 = g_row_start[node + 1];
    float4 acc = make_float4(0.f, 0.f, 0.f, 0.f);
    for (; j + 1 < s1; j += 2) {
        int sa = __ldg(&g_esrc[j]);
        int sb = __ldg(&g_esrc[j + 1]);
        float4 va = __ldg(reinterpret_cast<const float4*>(msg + (size_t)sa * HDIM + c * 4));
        float4 vb = __ldg(reinterpret_cast<const float4*>(msg + (size_t)sb * HDIM + c * 4));
        if (MODE == 0) {
            float na = __ldg(&g_norm_src[sa]);
            float nb = __ldg(&g_norm_src[sb]);
            acc.x = fmaf(va.x, na, acc.x); acc.y = fmaf(va.y, na, acc.y);
            acc.z = fmaf(va.z, na, acc.z); acc.w = fmaf(va.w, na, acc.w);
            acc.x = fmaf(vb.x, nb, acc.x); acc.y = fmaf(vb.y, nb, acc.y);
            acc.z = fmaf(vb.z, nb, acc.z); acc.w = fmaf(vb.w, nb, acc.w);
        } else {
            acc.x += va.x; acc.y += va.y; acc.z += va.z; acc.w += va.w;
            acc.x += vb.x; acc.y += vb.y; acc.z += vb.z; acc.w += vb.w;
        }
    }
    if (j < s1) {
        int sa = __ldg(&g_esrc[j]);
        float4 va = __ldg(reinterpret_cast<const float4*>(msg + (size_t)sa * HDIM + c * 4));
        if (MODE == 0) {
            float na = __ldg(&g_norm_src[sa]);
            acc.x = fmaf(va.x, na, acc.x); acc.y = fmaf(va.y, na, acc.y);
            acc.z = fmaf(va.z, na, acc.z); acc.w = fmaf(va.w, na, acc.w);
        } else {
            acc.x += va.x; acc.y += va.y; acc.z += va.z; acc.w += va.w;
        }
    }
    float nd = g_norm_dst[node];
    if (MODE == 0) {
        float ns = g_norm_src[node];
        float4 o;
        o.x = fmaxf(acc.x * nd, 0.f) * ns;
        o.y = fmaxf(acc.y * nd, 0.f) * ns;
        o.z = fmaxf(acc.z * nd, 0.f) * ns;
        o.w = fmaxf(acc.w * nd, 0.f) * ns;
        reinterpret_cast<float4*>(outf)[(size_t)node * 16 + c] = o;
    } else {
        uint32_t h01, l01, h23, l23;
        split2(acc.x * nd, acc.y * nd, h01, l01);
        split2(acc.z * nd, acc.w * nd, h23, l23);
        size_t off = ((size_t)node * HDIM + c * 4) >> 2;
        reinterpret_cast<uint2*>(outh)[off] = make_uint2(h01, h23);
        reinterpret_cast<uint2*>(outl)[off] = make_uint2(l01, l23);
    }
}

// ---------------- GEMM1: C[M,64] = A(fp32)[M,512] @ W1 (UNscaled output) ----------------
#define AST 40
__global__ __launch_bounds__(256) void gemm1_kernel(const float* __restrict__ A,
                                                    const unsigned short* __restrict__ Bth,
                                                    const unsigned short* __restrict__ Btl,
                                                    float* __restrict__ C, int M) {
    __shared__ __align__(16) unsigned short sAh[128 * AST];
    __shared__ __align__(16) unsigned short sAl[128 * AST];
    __shared__ __align__(16) unsigned short sBh[64 * AST];
    __shared__ __align__(16) unsigned short sBl[64 * AST];

    const int tid = threadIdx.x;
    const int wid = tid >> 5, lid = tid & 31;
    const int wm = wid & 3, wn = wid >> 2;
    const int block_m = blockIdx.x * 128;

    float acc[2][4][4];
#pragma unroll
    for (int i = 0; i < 2; i++)
#pragma unroll
        for (int j = 0; j < 4; j++)
#pragma unroll
            for (int q = 0; q < 4; q++) acc[i][j][q] = 0.f;

    const uint32_t aH = smem_to_u32(sAh);
    const uint32_t aL = smem_to_u32(sAl);
    const uint32_t bH = smem_to_u32(sBh);
    const uint32_t bL = smem_to_u32(sBl);

    const int b_n = tid >> 2, b_k8 = (tid & 3) * 8;
    for (int k0 = 0; k0 < FDIM; k0 += 32) {
#pragma unroll
        for (int it = 0; it < 4; it++) {
            int f = it * 256 + tid;
            int r = f >> 3, c4 = f & 7;
            int gr = block_m + r;
            float4 v = make_float4(0.f, 0.f, 0.f, 0.f);
            if (gr < M)
                v = __ldg(reinterpret_cast<const float4*>(A + (size_t)gr * FDIM + k0 + c4 * 4));
            uint32_t h01, l01, h23, l23;
            split2(v.x, v.y, h01, l01);
            split2(v.z, v.w, h23, l23);
            *reinterpret_cast<uint2*>(&sAh[r * AST + c4 * 4]) = make_uint2(h01, h23);
            *reinterpret_cast<uint2*>(&sAl[r * AST + c4 * 4]) = make_uint2(l01, l23);
        }
        {
            const size_t go = (size_t)b_n * FDIM + k0 + b_k8;
            uint4 vh = __ldg(reinterpret_cast<const uint4*>(Bth + go));
            uint4 vl = __ldg(reinterpret_cast<const uint4*>(Btl + go));
            *reinterpret_cast<uint4*>(&sBh[b_n * AST + b_k8]) = vh;
            *reinterpret_cast<uint4*>(&sBl[b_n * AST + b_k8]) = vl;
        }
        __syncthreads();

#pragma unroll
        for (int ks = 0; ks < 32; ks += 16) {
            uint32_t ah[2][4], al[2][4], bh[4][2], bl[4][2];
#pragma unroll
            for (int mf = 0; mf < 2; mf++) {
                uint32_t rowA = wm * 32 + mf * 16 + (lid & 15);
                uint32_t off = (rowA * AST + ks + (lid >> 4) * 8) * 2;
                ldsm4(ah[mf], aH + off);
                ldsm4(al[mf], aL + off);
            }
#pragma unroll
            for (int p = 0; p < 2; p++) {
                uint32_t nrow = wn * 32 + p * 16 + ((lid >> 4) & 1) * 8 + (lid & 7);
                uint32_t off = (nrow * AST + ks + ((lid >> 3) & 1) * 8) * 2;
                uint32_t r[4];
                ldsm4(r, bH + off);
                bh[2 * p][0] = r[0]; bh[2 * p][1] = r[1];
                bh[2 * p + 1][0] = r[2]; bh[2 * p + 1][1] = r[3];
                ldsm4(r, bL + off);
                bl[2 * p][0] = r[0]; bl[2 * p][1] = r[1];
                bl[2 * p + 1][0] = r[2]; bl[2 * p + 1][1] = r[3];
            }
#pragma unroll
            for (int mf = 0; mf < 2; mf++)
#pragma unroll
                for (int nf = 0; nf < 4; nf++) {
                    mma_bf16(acc[mf][nf], ah[mf], bh[nf]);
                    mma_bf16(acc[mf][nf], ah[mf], bl[nf]);
                    mma_bf16(acc[mf][nf], al[mf], bh[nf]);
                }
        }
        __syncthreads();
    }

    int lrow = lid >> 2, lcol = (lid & 3) * 2;
#pragma unroll
    for (int mf = 0; mf < 2; mf++)
#pragma unroll
        for (int half = 0; half < 2; half++) {
            int row = block_m + wm * 32 + mf * 16 + lrow + half * 8;
            if (row < M) {
#pragma unroll
                for (int nf = 0; nf < 4; nf++) {
                    int col = wn * 32 + nf * 8 + lcol;
                    float2 o = make_float2(acc[mf][nf][half * 2],
                                           acc[mf][nf][half * 2 + 1]);
                    *reinterpret_cast<float2*>(C + (size_t)row * HDIM + col) = o;
                }
            }
        }
}

// ---------------- GEMM2: C[M,512] = A(pre-split bf16)[M,64] @ W2 ----------------
#define AST2 72
#define G2_SMEM (2 * 128 * AST2 * 2 + 2 * 64 * AST2 * 2)
__global__ __launch_bounds__(256) void gemm2_kernel(const unsigned short* __restrict__ Ah,
                                                    const unsigned short* __restrict__ Al,
                                                    const unsigned short* __restrict__ Bth,
                                                    const unsigned short* __restrict__ Btl,
                                                    float* __restrict__ C, int M) {
    extern __shared__ __align__(16) unsigned short dyn[];
    unsigned short* sAh = dyn;
    unsigned short* sAl = sAh + 128 * AST2;
    unsigned short* sBh = sAl + 128 * AST2;
    unsigned short* sBl = sBh + 64 * AST2;

    const int tid = threadIdx.x;
    const int wid = tid >> 5, lid = tid & 31;
    const int wm = wid & 3, wn = wid >> 2;
    const int block_m = blockIdx.x * 128;

    const uint32_t aH = smem_to_u32(sAh);
    const uint32_t aL = smem_to_u32(sAl);
    const uint32_t bH = smem_to_u32(sBh);
    const uint32_t bL = smem_to_u32(sBl);

#pragma unroll
    for (int it = 0; it < 4; it++) {
        int u = it * 256 + tid;
        int r = u >> 3, q8 = (u & 7) * 8;
        int gr = block_m + r;
        uint4 vh = make_uint4(0, 0, 0, 0), vl = make_uint4(0, 0, 0, 0);
        if (gr < M) {
            size_t go = (size_t)gr * HDIM + q8;
            vh = __ldg(reinterpret_cast<const uint4*>(Ah + go));
            vl = __ldg(reinterpret_cast<const uint4*>(Al + go));
        }
        *reinterpret_cast<uint4*>(&sAh[r * AST2 + q8]) = vh;
        *reinterpret_cast<uint4*>(&sAl[r * AST2 + q8]) = vl;
    }

    int lrow = lid >> 2, lcol = (lid & 3) * 2;

    for (int nt = 0; nt < FDIM / 64; nt++) {
        const int n0 = nt * 64;
        __syncthreads();
#pragma unroll
        for (int it = 0; it < 2; it++) {
            int u = it * 256 + tid;
            int r = u >> 3, q8 = (u & 7) * 8;
            size_t go = (size_t)(n0 + r) * HDIM + q8;
            uint4 vh = __ldg(reinterpret_cast<const uint4*>(Bth + go));
            uint4 vl = __ldg(reinterpret_cast<const uint4*>(Btl + go));
            *reinterpret_cast<uint4*>(&sBh[r * AST2 + q8]) = vh;
            *reinterpret_cast<uint4*>(&sBl[r * AST2 + q8]) = vl;
        }
        __syncthreads();

        float acc[2][4][4];
#pragma unroll
        for (int i = 0; i < 2; i++)
#pragma unroll
            for (int j = 0; j < 4; j++)
#pragma unroll
                for (int q = 0; q < 4; q++) acc[i][j][q] = 0.f;

#pragma unroll
        for (int ks = 0; ks < 64; ks += 16) {
            uint32_t ah[2][4], al[2][4], bh[4][2], bl[4][2];
#pragma unroll
            for (int mf = 0; mf < 2; mf++) {
                uint32_t rowA = wm * 32 + mf * 16 + (lid & 15);
                uint32_t off = (rowA * AST2 + ks + (lid >> 4) * 8) * 2;
                ldsm4(ah[mf], aH + off);
                ldsm4(al[mf], aL + off);
            }
#pragma unroll
            for (int p = 0; p < 2; p++) {
                uint32_t nrow = wn * 32 + p * 16 + ((lid >> 4) & 1) * 8 + (lid & 7);
                uint32_t off = (nrow * AST2 + ks + ((lid >> 3) & 1) * 8) * 2;
                uint32_t r[4];
                ldsm4(r, bH + off);
                bh[2 * p][0] = r[0]; bh[2 * p][1] = r[1];
                bh[2 * p + 1][0] = r[2]; bh[2 * p + 1][1] = r[3];
                ldsm4(r, bL + off);
                bl[2 * p][0] = r[0]; bl[2 * p][1] = r[1];
                bl[2 * p + 1][0] = r[2]; bl[2 * p + 1][1] = r[3];
            }
#pragma unroll
            for (int mf = 0; mf < 2; mf++)
#pragma unroll
                for (int nf = 0; nf < 4; nf++) {
                    mma_bf16(acc[mf][nf], ah[mf], bh[nf]);
                    mma_bf16(acc[mf][nf], ah[mf], bl[nf]);
                    mma_bf16(acc[mf][nf], al[mf], bh[nf]);
                }
        }

#pragma unroll
        for (int mf = 0; mf < 2; mf++)
#pragma unroll
            for (int half = 0; half < 2; half++) {
                int row = block_m + wm * 32 + mf * 16 + lrow + half * 8;
                if (row < M) {
#pragma unroll
                    for (int nf = 0; nf < 4; nf++) {
                        int col = n0 + wn * 32 + nf * 8 + lcol;
                        float2 o = make_float2(acc[mf][nf][half * 2],
                                               acc[mf][nf][half * 2 + 1]);
                        *reinterpret_cast<float2*>(C + (size_t)row * FDIM + col) = o;
                    }
                }
            }
    }
}

// ---------------- streams/events (created once, before harness baselines) ----------------
static cudaStream_t g_s2;
static cudaEvent_t g_evF, g_evJ;
static struct StreamInit {
    StreamInit() {
        cudaStreamCreateWithFlags(&g_s2, cudaStreamNonBlocking);
        cudaEventCreateWithFlags(&g_evF, cudaEventDisableTiming);
        cudaEventCreateWithFlags(&g_evJ, cudaEventDisableTiming);
    }
} g_stream_init;

// ---------------- launch ----------------
extern "C" void kernel_launch(void* const* d_in, const int* in_sizes, int n_in,
                              void* d_out, int out_size) {
    const float* features = (const float*)d_in[0];
    const void* src = d_in[1];
    const void* dst = d_in[2];
    const float* W1 = (const float*)d_in[3];
    const float* W2 = (const float*)d_in[4];
    float* out = (float*)d_out;

    const int N = N_NODES;
    const int E = in_sizes[1];

    float *p_x1g, *p_hs;
    unsigned short *p_a2h, *p_a2l, *p_w1ht, *p_w1lt, *p_w2ht, *p_w2lt;
    cudaGetSymbolAddress((void**)&p_x1g, g_x1g);
    cudaGetSymbolAddress((void**)&p_hs, g_hs);
    cudaGetSymbolAddress((void**)&p_a2h, g_a2h);
    cudaGetSymbolAddress((void**)&p_a2l, g_a2l);
    cudaGetSymbolAddress((void**)&p_w1ht, g_w1ht);
    cudaGetSymbolAddress((void**)&p_w1lt, g_w1lt);
    cudaGetSymbolAddress((void**)&p_w2ht, g_w2ht);
    cudaGetSymbolAddress((void**)&p_w2lt, g_w2lt);

    cudaFuncSetAttribute(gemm2_kernel, cudaFuncAttributeMaxDynamicSharedMemorySize, G2_SMEM);

    const int nb_scan = (N + 1023) / 1024;
    const int mtiles = (N + 127) / 128;

    // ---- fork: wconv + GEMM1 on side stream (independent of graph build) ----
    cudaEventRecord(g_evF, 0);
    cudaStreamWaitEvent(g_s2, g_evF, 0);
    wconv_kernel<<<(FDIM * HDIM + 255) / 256, 256, 0, g_s2>>>(W1, W2);
    gemm1_kernel<<<mtiles, 256, 0, g_s2>>>(features, p_w1ht, p_w1lt, p_x1g, N);
    cudaEventRecord(g_evJ, g_s2);

    // ---- main stream: graph build (CSR + norms) ----
    zero_counts_kernel<<<(N + 255) / 256, 256>>>((const int*)src, (const int*)dst, N, E);
    hist_kernel<<<(E + 255) / 256, 256>>>(src, dst, E);
    scan1_kernel<<<nb_scan, 256>>>(N);
    scan2_kernel<<<1, 256>>>(nb_scan);
    scan3_kernel<<<(N + 255) / 256, 256>>>(N, E);
    fill_kernel<<<(E + 255) / 256, 256>>>(src, dst, E);

    // ---- join, then aggregations + GEMM2 ----
    cudaStreamWaitEvent(0, g_evJ, 0);
    agg_kernel<0><<<(N + 15) / 16, 256>>>(p_x1g, p_hs, nullptr, nullptr, N);
    agg_kernel<1><<<(N + 15) / 16, 256>>>(p_hs, nullptr, p_a2h, p_a2l, N);
    gemm2_kernel<<<mtiles, 256, G2_SMEM>>>(p_a2h, p_a2l, p_w2ht, p_w2lt, out, N);
}